// round 2
// baseline (speedup 1.0000x reference)
#include <cuda_runtime.h>
#include <cstdint>

#define NN 100000
#define NE 1600000
#define DH 64

// ---------------- scratch (no allocations allowed) ----------------
__device__ float g_agg[(size_t)NN * DH];
__device__ float g_h1 [(size_t)NN * DH];
__device__ float g_h2 [(size_t)NN * DH];
__device__ float g_Wt1[128 * 64];   // [k][n] concat of W1_rel^T ; W1_root^T
__device__ float g_Wt2[128 * 64];
__device__ int   g_src[NE];
__device__ int   g_dst[NE];
__device__ int   g_is64;

// ---------------- dtype detection: is edge_index int64 or int32? ----------
// int64 data: each 8-byte word is a node id in [0, NN).
// int32 data read as int64: lo | hi<<32 with hi a random node id -> huge.
__global__ void detect_idx(const void* __restrict__ ei) {
    if (threadIdx.x == 0 && blockIdx.x == 0) {
        const long long* p = (const long long*)ei;
        bool all64 = true;
        #pragma unroll
        for (int i = 0; i < 8; ++i) {
            long long v = p[i];
            if (v < 0 || v >= NN) all64 = false;
        }
        g_is64 = all64 ? 1 : 0;
    }
}

// ---------------- convert edge_index -> compact int32 src/dst -------------
__global__ void convert_idx(const void* __restrict__ ei,
                            int* __restrict__ src, int* __restrict__ dst) {
    int i = blockIdx.x * blockDim.x + threadIdx.x;
    if (i >= NE) return;
    if (g_is64) {
        const long long* p = (const long long*)ei;
        src[i] = (int)p[i];
        dst[i] = (int)p[NE + i];
    } else {
        const int* p = (const int*)ei;
        src[i] = p[i];
        dst[i] = p[NE + i];
    }
}

// ---------------- tiny prep: Wt[k][n] = k<64 ? Wrel[n][k] : Wroot[n][k-64] ----
__global__ void prep_w(const float* __restrict__ Wrel,
                       const float* __restrict__ Wroot,
                       float* __restrict__ Wt) {
    int i = blockIdx.x * blockDim.x + threadIdx.x;   // 0..8191
    if (i < 128 * 64) {
        int k = i >> 6;
        int n = i & 63;
        Wt[i] = (k < 64) ? Wrel[n * 64 + k] : Wroot[n * 64 + (k - 64)];
    }
}

// ---------------- zero the aggregation buffer ----------------
__global__ void zero_buf(float4* __restrict__ p, int n4) {
    int i = blockIdx.x * blockDim.x + threadIdx.x;
    if (i < n4) p[i] = make_float4(0.f, 0.f, 0.f, 0.f);
}

// ---------------- scatter-add: agg[dst] += feat[src] ----------------
// 16 threads per edge, each handles one float4 (4 features).
__global__ void scatter_add(const float* __restrict__ feat,
                            const int* __restrict__ src,
                            const int* __restrict__ dst,
                            float* __restrict__ agg) {
    unsigned q = blockIdx.x * blockDim.x + threadIdx.x;
    if (q >= (unsigned)NE * 16u) return;
    int e = q >> 4;
    int c = (q & 15) << 2;
    int s = src[e];
    int d = dst[e];
    float4 v = *reinterpret_cast<const float4*>(feat + (size_t)s * DH + c);
    float* p = agg + (size_t)d * DH + c;
    atomicAdd(p + 0, v.x);
    atomicAdd(p + 1, v.y);
    atomicAdd(p + 2, v.z);
    atomicAdd(p + 3, v.w);
}

// ---------------- fused layer GEMM ----------------
// out[m][n] = relu( sum_k agg[m][k]*Wt[k][n] (k<64)  +  sum_k xin[m][k]*Wt[64+k][n]  + bias[n] )
// BM=128, BN=64, K=128 (two chunks of 64). 128 threads, 8x8 micro-tile.
// As layout: [m][68] (pad 4 floats -> strided-m a-loads hit 4 distinct banks).
#define AS_STRIDE 68

__global__ void __launch_bounds__(128, 3)
gemm_fused(const float* __restrict__ A0,   // agg  [NN,64]
           const float* __restrict__ A1,   // xin  [NN,64]
           const float* __restrict__ Wt,   // [128,64] (k-major)
           const float* __restrict__ bias, // [64]
           float* __restrict__ out) {      // [NN,64]
    extern __shared__ float sm[];
    float* Bs = sm;                    // [128][64]   = 8192 floats
    float* As = sm + 128 * 64;         // [128][68]   = 8704 floats

    const int tid = threadIdx.x;
    const int tn  = tid & 7;           // 0..7  (n-tile)
    const int tm  = tid >> 3;          // 0..15 (m-tile, strided by 16)
    const int m0  = blockIdx.x * 128;

    // load full weight tile (k-major, conflict-free float4)
    #pragma unroll
    for (int i = tid; i < 128 * 64 / 4; i += 128)
        reinterpret_cast<float4*>(Bs)[i] = reinterpret_cast<const float4*>(Wt)[i];

    float acc[8][8];
    #pragma unroll
    for (int i = 0; i < 8; ++i)
        #pragma unroll
        for (int j = 0; j < 8; ++j) acc[i][j] = 0.f;

    #pragma unroll
    for (int ch = 0; ch < 2; ++ch) {
        const float* A = ch ? A1 : A0;
        __syncthreads();   // protects Bs on first pass, As re-use on second
        // stage As[m][k] for this 64-wide k chunk (coalesced float4 reads)
        #pragma unroll
        for (int r = 0; r < 16; ++r) {
            int idx = r * 128 + tid;       // 0..2047 float4 slots (128 rows x 16)
            int m   = idx >> 4;
            int q   = idx & 15;
            int gm  = m0 + m;
            float4 v = (gm < NN)
                ? *reinterpret_cast<const float4*>(A + (size_t)gm * DH + q * 4)
                : make_float4(0.f, 0.f, 0.f, 0.f);
            *reinterpret_cast<float4*>(As + m * AS_STRIDE + q * 4) = v;
        }
        __syncthreads();

        const float* Bc = Bs + ch * 64 * 64;
        #pragma unroll 4
        for (int k = 0; k < 64; ++k) {
            const float* brow = Bc + k * 64 + tn * 8;
            float4 b0 = *reinterpret_cast<const float4*>(brow);
            float4 b1 = *reinterpret_cast<const float4*>(brow + 4);
            #pragma unroll
            for (int i = 0; i < 8; ++i) {
                float a = As[(tm + 16 * i) * AS_STRIDE + k];
                acc[i][0] += a * b0.x;  acc[i][1] += a * b0.y;
                acc[i][2] += a * b0.z;  acc[i][3] += a * b0.w;
                acc[i][4] += a * b1.x;  acc[i][5] += a * b1.y;
                acc[i][6] += a * b1.z;  acc[i][7] += a * b1.w;
            }
        }
    }

    // epilogue: + bias, relu, store
    float4 bb0 = *reinterpret_cast<const float4*>(bias + tn * 8);
    float4 bb1 = *reinterpret_cast<const float4*>(bias + tn * 8 + 4);
    #pragma unroll
    for (int i = 0; i < 8; ++i) {
        int gm = m0 + tm + 16 * i;
        if (gm < NN) {
            float4 o0, o1;
            o0.x = fmaxf(acc[i][0] + bb0.x, 0.f);
            o0.y = fmaxf(acc[i][1] + bb0.y, 0.f);
            o0.z = fmaxf(acc[i][2] + bb0.z, 0.f);
            o0.w = fmaxf(acc[i][3] + bb0.w, 0.f);
            o1.x = fmaxf(acc[i][4] + bb1.x, 0.f);
            o1.y = fmaxf(acc[i][5] + bb1.y, 0.f);
            o1.z = fmaxf(acc[i][6] + bb1.z, 0.f);
            o1.w = fmaxf(acc[i][7] + bb1.w, 0.f);
            float* po = out + (size_t)gm * DH + tn * 8;
            *reinterpret_cast<float4*>(po)     = o0;
            *reinterpret_cast<float4*>(po + 4) = o1;
        }
    }
}

// ---------------- final head: out[n][o] = h2[n] . W_lin[o] + b_lin[o] (o<3) ----
__global__ void final_lin(const float* __restrict__ h,
                          const float* __restrict__ W,   // [3,64]
                          const float* __restrict__ b,   // [3]
                          float* __restrict__ out) {     // [NN,3]
    __shared__ float Ws[3 * 64];
    __shared__ float hs[64 * 64];
    int tid = threadIdx.x;     // 256
    if (tid < 192) Ws[tid] = W[tid];
    int n0 = blockIdx.x * 64;
    #pragma unroll
    for (int r = 0; r < 4; ++r) {
        int idx = r * 256 + tid;      // float4 slot 0..1023
        int m = idx >> 4, q = idx & 15;
        int gm = n0 + m;
        float4 v = (gm < NN)
            ? reinterpret_cast<const float4*>(h + (size_t)gm * DH)[q]
            : make_float4(0.f, 0.f, 0.f, 0.f);
        reinterpret_cast<float4*>(hs)[idx] = v;
    }
    __syncthreads();
    if (tid < 192) {
        int m = tid / 3;
        int o = tid - 3 * m;
        int gm = n0 + m;
        if (gm < NN) {
            float s = b[o];
            #pragma unroll 16
            for (int k = 0; k < 64; ++k) s += hs[m * 64 + k] * Ws[o * 64 + k];
            out[(size_t)gm * 3 + o] = s;
        }
    }
}

// ---------------- launch ----------------
extern "C" void kernel_launch(void* const* d_in, const int* in_sizes, int n_in,
                              void* d_out, int out_size) {
    const float* x      = (const float*)d_in[0];
    const void*  ei     = d_in[1];                 // int32 OR int64, detected on device
    const float* W1_rel = (const float*)d_in[2];
    const float* b1     = (const float*)d_in[3];
    const float* W1_rt  = (const float*)d_in[4];
    const float* W2_rel = (const float*)d_in[5];
    const float* b2     = (const float*)d_in[6];
    const float* W2_rt  = (const float*)d_in[7];
    const float* W_lin  = (const float*)d_in[8];
    const float* b_lin  = (const float*)d_in[9];
    float*       out    = (float*)d_out;

    float *agg, *h1, *h2, *Wt1, *Wt2;
    int *src, *dst;
    cudaGetSymbolAddress((void**)&agg, g_agg);
    cudaGetSymbolAddress((void**)&h1,  g_h1);
    cudaGetSymbolAddress((void**)&h2,  g_h2);
    cudaGetSymbolAddress((void**)&Wt1, g_Wt1);
    cudaGetSymbolAddress((void**)&Wt2, g_Wt2);
    cudaGetSymbolAddress((void**)&src, g_src);
    cudaGetSymbolAddress((void**)&dst, g_dst);

    const int smem = (128 * 64 + 128 * AS_STRIDE) * sizeof(float);   // 67584 B
    cudaFuncSetAttribute(gemm_fused, cudaFuncAttributeMaxDynamicSharedMemorySize, smem);

    const int zgrid = (NN * DH / 4 + 255) / 256;          // zero: float4 count
    const int sgrid = (int)(((unsigned)NE * 16u + 255u) / 256u); // scatter
    const int ggrid = (NN + 127) / 128;                   // gemm
    const int fgrid = (NN + 63) / 64;                     // final
    const int cgrid = (NE + 255) / 256;                   // convert

    detect_idx<<<1, 32>>>(ei);
    convert_idx<<<cgrid, 256>>>(ei, src, dst);
    prep_w<<<32, 256>>>(W1_rel, W1_rt, Wt1);
    prep_w<<<32, 256>>>(W2_rel, W2_rt, Wt2);

    // layer 1
    zero_buf<<<zgrid, 256>>>((float4*)agg, NN * DH / 4);
    scatter_add<<<sgrid, 256>>>(x, src, dst, agg);
    gemm_fused<<<ggrid, 128, smem>>>(agg, x, Wt1, b1, h1);

    // layer 2
    zero_buf<<<zgrid, 256>>>((float4*)agg, NN * DH / 4);
    scatter_add<<<sgrid, 256>>>(h1, src, dst, agg);
    gemm_fused<<<ggrid, 128, smem>>>(agg, h1, Wt2, b2, h2);

    // head
    final_lin<<<fgrid, 256>>>(h2, W_lin, b_lin, out);
}

// round 3
// speedup vs baseline: 2.3297x; 2.3297x over previous
#include <cuda_runtime.h>
#include <cstdint>

#define NN 100000
#define NE 1600000
#define DH 64
#define SCAN_BLK 1024                       // counts per scan block
#define NB ((NN + SCAN_BLK - 1) / SCAN_BLK) // 98

// ---------------- scratch (no allocations allowed) ----------------
__device__ float g_agg[(size_t)NN * DH];
__device__ float g_h1 [(size_t)NN * DH];
__device__ float g_h2 [(size_t)NN * DH];
__device__ float g_Wt1[128 * 64];
__device__ float g_Wt2[128 * 64];
__device__ int   g_src[NE];
__device__ int   g_dst[NE];
__device__ int   g_esrc[NE];      // src ids grouped by dst (CSR)
__device__ int   g_cnt[NN];
__device__ int   g_offs[NN + 1];
__device__ int   g_cursor[NN];
__device__ int   g_bsum[NB];
__device__ int   g_is64;

// ---------------- dtype detection: int64 vs int32 edge_index --------------
__global__ void detect_idx(const void* __restrict__ ei) {
    if (threadIdx.x == 0 && blockIdx.x == 0) {
        const long long* p = (const long long*)ei;
        bool all64 = true;
        #pragma unroll
        for (int i = 0; i < 8; ++i) {
            long long v = p[i];
            if (v < 0 || v >= NN) all64 = false;
        }
        g_is64 = all64 ? 1 : 0;
    }
}

// ---------------- convert edge_index -> compact int32 src/dst -------------
__global__ void convert_idx(const void* __restrict__ ei,
                            int* __restrict__ src, int* __restrict__ dst) {
    int i = blockIdx.x * blockDim.x + threadIdx.x;
    if (i >= NE) return;
    if (g_is64) {
        const long long* p = (const long long*)ei;
        src[i] = (int)p[i];
        dst[i] = (int)p[NE + i];
    } else {
        const int* p = (const int*)ei;
        src[i] = p[i];
        dst[i] = p[NE + i];
    }
}

// ---------------- CSR build ----------------
__global__ void zero_int(int* __restrict__ p, int n) {
    int i = blockIdx.x * blockDim.x + threadIdx.x;
    if (i < n) p[i] = 0;
}

__global__ void hist_dst(const int* __restrict__ dst, int* __restrict__ cnt) {
    int i = blockIdx.x * blockDim.x + threadIdx.x;
    if (i < NE) atomicAdd(&cnt[dst[i]], 1);
}

// per-block exclusive scan: 256 threads x 4 counts = 1024/block
__global__ void scan_blocks(const int* __restrict__ cnt,
                            int* __restrict__ offs, int* __restrict__ bsum) {
    __shared__ int sh[256];
    int t = threadIdx.x;
    int base = blockIdx.x * SCAN_BLK + t * 4;
    int c0 = (base + 0 < NN) ? cnt[base + 0] : 0;
    int c1 = (base + 1 < NN) ? cnt[base + 1] : 0;
    int c2 = (base + 2 < NN) ? cnt[base + 2] : 0;
    int c3 = (base + 3 < NN) ? cnt[base + 3] : 0;
    int s = c0 + c1 + c2 + c3;
    sh[t] = s;
    __syncthreads();
    #pragma unroll
    for (int off = 1; off < 256; off <<= 1) {
        int v = (t >= off) ? sh[t - off] : 0;
        __syncthreads();
        sh[t] += v;
        __syncthreads();
    }
    int excl = sh[t] - s;
    if (t == 255) bsum[blockIdx.x] = sh[255];
    if (base + 0 < NN) offs[base + 0] = excl;  excl += c0;
    if (base + 1 < NN) offs[base + 1] = excl;  excl += c1;
    if (base + 2 < NN) offs[base + 2] = excl;  excl += c2;
    if (base + 3 < NN) offs[base + 3] = excl;
}

__global__ void scan_bsums(int* __restrict__ bsum) {
    if (threadIdx.x == 0 && blockIdx.x == 0) {
        int run = 0;
        for (int b = 0; b < NB; ++b) { int t = bsum[b]; bsum[b] = run; run += t; }
    }
}

__global__ void add_base(int* __restrict__ offs, const int* __restrict__ bsum,
                         int* __restrict__ cursor) {
    int i = blockIdx.x * blockDim.x + threadIdx.x;
    if (i < NN) {
        int v = offs[i] + bsum[i / SCAN_BLK];
        offs[i] = v;
        cursor[i] = v;
    }
    if (i == 0) offs[NN] = NE;
}

__global__ void place_edges(const int* __restrict__ src, const int* __restrict__ dst,
                            int* __restrict__ cursor, int* __restrict__ esrc) {
    int i = blockIdx.x * blockDim.x + threadIdx.x;
    if (i >= NE) return;
    int p = atomicAdd(&cursor[dst[i]], 1);
    esrc[p] = src[i];
}

// ---------------- gather aggregation: agg[n] = sum_{e in CSR(n)} feat[esrc[e]] ----
// one warp per node; each lane owns a float2 column pair; 4-edge unroll for MLP.
__global__ void __launch_bounds__(256)
gather_agg(const float* __restrict__ feat,
           const int* __restrict__ offs,
           const int* __restrict__ esrc,
           float* __restrict__ agg) {
    int node = blockIdx.x * (blockDim.x >> 5) + (threadIdx.x >> 5);
    if (node >= NN) return;
    int lane = threadIdx.x & 31;
    int s0 = offs[node];
    int s1 = offs[node + 1];
    const float2* f2 = reinterpret_cast<const float2*>(feat);
    float sx = 0.f, sy = 0.f;
    int j = s0;
    for (; j + 4 <= s1; j += 4) {
        int a = esrc[j], b = esrc[j + 1], c = esrc[j + 2], d = esrc[j + 3];
        float2 v0 = f2[(size_t)a * 32 + lane];
        float2 v1 = f2[(size_t)b * 32 + lane];
        float2 v2 = f2[(size_t)c * 32 + lane];
        float2 v3 = f2[(size_t)d * 32 + lane];
        sx += v0.x + v1.x + v2.x + v3.x;
        sy += v0.y + v1.y + v2.y + v3.y;
    }
    for (; j < s1; ++j) {
        int a = esrc[j];
        float2 v = f2[(size_t)a * 32 + lane];
        sx += v.x; sy += v.y;
    }
    reinterpret_cast<float2*>(agg)[(size_t)node * 32 + lane] = make_float2(sx, sy);
}

// ---------------- tiny prep: Wt[k][n] = k<64 ? Wrel[n][k] : Wroot[n][k-64] ----
__global__ void prep_w(const float* __restrict__ Wrel,
                       const float* __restrict__ Wroot,
                       float* __restrict__ Wt) {
    int i = blockIdx.x * blockDim.x + threadIdx.x;
    if (i < 128 * 64) {
        int k = i >> 6;
        int n = i & 63;
        Wt[i] = (k < 64) ? Wrel[n * 64 + k] : Wroot[n * 64 + (k - 64)];
    }
}

// ---------------- fused layer GEMM (unchanged from R2) ----------------
#define AS_STRIDE 68

__global__ void __launch_bounds__(128, 3)
gemm_fused(const float* __restrict__ A0,   // agg  [NN,64]
           const float* __restrict__ A1,   // xin  [NN,64]
           const float* __restrict__ Wt,   // [128,64] (k-major)
           const float* __restrict__ bias, // [64]
           float* __restrict__ out) {      // [NN,64]
    extern __shared__ float sm[];
    float* Bs = sm;                    // [128][64]
    float* As = sm + 128 * 64;         // [128][68]

    const int tid = threadIdx.x;
    const int tn  = tid & 7;
    const int tm  = tid >> 3;
    const int m0  = blockIdx.x * 128;

    #pragma unroll
    for (int i = tid; i < 128 * 64 / 4; i += 128)
        reinterpret_cast<float4*>(Bs)[i] = reinterpret_cast<const float4*>(Wt)[i];

    float acc[8][8];
    #pragma unroll
    for (int i = 0; i < 8; ++i)
        #pragma unroll
        for (int j = 0; j < 8; ++j) acc[i][j] = 0.f;

    #pragma unroll
    for (int ch = 0; ch < 2; ++ch) {
        const float* A = ch ? A1 : A0;
        __syncthreads();
        #pragma unroll
        for (int r = 0; r < 16; ++r) {
            int idx = r * 128 + tid;
            int m   = idx >> 4;
            int q   = idx & 15;
            int gm  = m0 + m;
            float4 v = (gm < NN)
                ? *reinterpret_cast<const float4*>(A + (size_t)gm * DH + q * 4)
                : make_float4(0.f, 0.f, 0.f, 0.f);
            *reinterpret_cast<float4*>(As + m * AS_STRIDE + q * 4) = v;
        }
        __syncthreads();

        const float* Bc = Bs + ch * 64 * 64;
        #pragma unroll 4
        for (int k = 0; k < 64; ++k) {
            const float* brow = Bc + k * 64 + tn * 8;
            float4 b0 = *reinterpret_cast<const float4*>(brow);
            float4 b1 = *reinterpret_cast<const float4*>(brow + 4);
            #pragma unroll
            for (int i = 0; i < 8; ++i) {
                float a = As[(tm + 16 * i) * AS_STRIDE + k];
                acc[i][0] += a * b0.x;  acc[i][1] += a * b0.y;
                acc[i][2] += a * b0.z;  acc[i][3] += a * b0.w;
                acc[i][4] += a * b1.x;  acc[i][5] += a * b1.y;
                acc[i][6] += a * b1.z;  acc[i][7] += a * b1.w;
            }
        }
    }

    float4 bb0 = *reinterpret_cast<const float4*>(bias + tn * 8);
    float4 bb1 = *reinterpret_cast<const float4*>(bias + tn * 8 + 4);
    #pragma unroll
    for (int i = 0; i < 8; ++i) {
        int gm = m0 + tm + 16 * i;
        if (gm < NN) {
            float4 o0, o1;
            o0.x = fmaxf(acc[i][0] + bb0.x, 0.f);
            o0.y = fmaxf(acc[i][1] + bb0.y, 0.f);
            o0.z = fmaxf(acc[i][2] + bb0.z, 0.f);
            o0.w = fmaxf(acc[i][3] + bb0.w, 0.f);
            o1.x = fmaxf(acc[i][4] + bb1.x, 0.f);
            o1.y = fmaxf(acc[i][5] + bb1.y, 0.f);
            o1.z = fmaxf(acc[i][6] + bb1.z, 0.f);
            o1.w = fmaxf(acc[i][7] + bb1.w, 0.f);
            float* po = out + (size_t)gm * DH + tn * 8;
            *reinterpret_cast<float4*>(po)     = o0;
            *reinterpret_cast<float4*>(po + 4) = o1;
        }
    }
}

// ---------------- final head ----------------
__global__ void final_lin(const float* __restrict__ h,
                          const float* __restrict__ W,   // [3,64]
                          const float* __restrict__ b,   // [3]
                          float* __restrict__ out) {     // [NN,3]
    __shared__ float Ws[3 * 64];
    __shared__ float hs[64 * 64];
    int tid = threadIdx.x;     // 256
    if (tid < 192) Ws[tid] = W[tid];
    int n0 = blockIdx.x * 64;
    #pragma unroll
    for (int r = 0; r < 4; ++r) {
        int idx = r * 256 + tid;
        int m = idx >> 4, q = idx & 15;
        int gm = n0 + m;
        float4 v = (gm < NN)
            ? reinterpret_cast<const float4*>(h + (size_t)gm * DH)[q]
            : make_float4(0.f, 0.f, 0.f, 0.f);
        reinterpret_cast<float4*>(hs)[idx] = v;
    }
    __syncthreads();
    if (tid < 192) {
        int m = tid / 3;
        int o = tid - 3 * m;
        int gm = n0 + m;
        if (gm < NN) {
            float s = b[o];
            #pragma unroll 16
            for (int k = 0; k < 64; ++k) s += hs[m * 64 + k] * Ws[o * 64 + k];
            out[(size_t)gm * 3 + o] = s;
        }
    }
}

// ---------------- launch ----------------
extern "C" void kernel_launch(void* const* d_in, const int* in_sizes, int n_in,
                              void* d_out, int out_size) {
    const float* x      = (const float*)d_in[0];
    const void*  ei     = d_in[1];
    const float* W1_rel = (const float*)d_in[2];
    const float* b1     = (const float*)d_in[3];
    const float* W1_rt  = (const float*)d_in[4];
    const float* W2_rel = (const float*)d_in[5];
    const float* b2     = (const float*)d_in[6];
    const float* W2_rt  = (const float*)d_in[7];
    const float* W_lin  = (const float*)d_in[8];
    const float* b_lin  = (const float*)d_in[9];
    float*       out    = (float*)d_out;

    float *agg, *h1, *h2, *Wt1, *Wt2;
    int *src, *dst, *esrc, *cnt, *offs, *cursor, *bsum;
    cudaGetSymbolAddress((void**)&agg,    g_agg);
    cudaGetSymbolAddress((void**)&h1,     g_h1);
    cudaGetSymbolAddress((void**)&h2,     g_h2);
    cudaGetSymbolAddress((void**)&Wt1,    g_Wt1);
    cudaGetSymbolAddress((void**)&Wt2,    g_Wt2);
    cudaGetSymbolAddress((void**)&src,    g_src);
    cudaGetSymbolAddress((void**)&dst,    g_dst);
    cudaGetSymbolAddress((void**)&esrc,   g_esrc);
    cudaGetSymbolAddress((void**)&cnt,    g_cnt);
    cudaGetSymbolAddress((void**)&offs,   g_offs);
    cudaGetSymbolAddress((void**)&cursor, g_cursor);
    cudaGetSymbolAddress((void**)&bsum,   g_bsum);

    const int smem = (128 * 64 + 128 * AS_STRIDE) * sizeof(float);   // 67584 B
    cudaFuncSetAttribute(gemm_fused, cudaFuncAttributeMaxDynamicSharedMemorySize, smem);

    const int egrid = (NE + 255) / 256;
    const int ngrid = (NN + 255) / 256;
    const int ggrid = (NN + 127) / 128;
    const int fgrid = (NN + 63) / 64;
    const int agrid = (NN + 7) / 8;         // gather: 8 warps/block

    // index ingest + CSR build (once per launch)
    detect_idx<<<1, 32>>>(ei);
    convert_idx<<<egrid, 256>>>(ei, src, dst);
    zero_int<<<ngrid, 256>>>(cnt, NN);
    hist_dst<<<egrid, 256>>>(dst, cnt);
    scan_blocks<<<NB, 256>>>(cnt, offs, bsum);
    scan_bsums<<<1, 32>>>(bsum);
    add_base<<<ngrid, 256>>>(offs, bsum, cursor);
    place_edges<<<egrid, 256>>>(src, dst, cursor, esrc);

    // weights prep
    prep_w<<<32, 256>>>(W1_rel, W1_rt, Wt1);
    prep_w<<<32, 256>>>(W2_rel, W2_rt, Wt2);

    // layer 1
    gather_agg<<<agrid, 256>>>(x, offs, esrc, agg);
    gemm_fused<<<ggrid, 128, smem>>>(agg, x, Wt1, b1, h1);

    // layer 2
    gather_agg<<<agrid, 256>>>(h1, offs, esrc, agg);
    gemm_fused<<<ggrid, 128, smem>>>(agg, h1, Wt2, b2, h2);

    // head
    final_lin<<<fgrid, 256>>>(h2, W_lin, b_lin, out);
}